// round 2
// baseline (speedup 1.0000x reference)
#include <cuda_runtime.h>
#include <cstdint>

#define BATCH 512
#define TSTEPS 1024
#define IDIM 64
#define HDIM 128

// Scratch (static __device__ arrays — no allocation in kernel_launch)
__device__ float g_xp[(size_t)TSTEPS * BATCH * HDIM];   // [t][b][h]  268 MB

typedef unsigned long long u64t;

__device__ __forceinline__ u64t ffma2(u64t a, u64t b, u64t c) {
    u64t d;
    asm("fma.rn.f32x2 %0, %1, %2, %3;" : "=l"(d) : "l"(a), "l"(b), "l"(c));
    return d;
}
__device__ __forceinline__ float f2lo(u64t v) { return __uint_as_float((unsigned)(v & 0xffffffffULL)); }
__device__ __forceinline__ float f2hi(u64t v) { return __uint_as_float((unsigned)(v >> 32)); }
__device__ __forceinline__ float tanh_ap(float x) {
    float y;
    asm("tanh.approx.f32 %0, %1;" : "=f"(y) : "f"(x));
    return y;
}

// ---------------------------------------------------------------------------
// Kernel 1: xp[t][b][j] = sum_i x[b][t][i] * W_ih[j][i] + (b_ih[j]+b_hh[j])
// 256 threads, CTA tile = 256 rows (4 blocks of 64) x 128 cols.
// thread (cg=tid>>4, rg=tid&15): 4 rows x 8 cols, f32x2 packed over row pairs.
// W_ih is splatted into shared per-CTA (no prep kernel).
// ---------------------------------------------------------------------------
__global__ void __launch_bounds__(256, 2) xproj_kernel(
    const float* __restrict__ x,
    const float* __restrict__ W_ih,
    const float* __restrict__ b_ih,
    const float* __restrict__ b_hh)
{
    extern __shared__ float smem[];
    float* sW = smem;               // [64][256]  (splatted W: sW[k][2j]=sW[k][2j+1]=W_ih[j][k])
    float* sX = smem + 64 * 256;    // [64][68]   (x transposed, padded)

    const int tid = threadIdx.x;
    const int cg = tid >> 4;        // 0..15 -> cols cg*8..cg*8+7
    const int rg = tid & 15;        // 0..15 -> rows rg*4..rg*4+3

    // Build splatted W in shared directly from W_ih (coalesced reads).
    #pragma unroll
    for (int i = 0; i < 32; i++) {
        int idx = tid + i * 256;     // 0..8191
        int j = idx >> 6;            // 0..127
        int k = idx & 63;            // 0..63
        float v = W_ih[idx];
        *(float2*)&sW[k * 256 + 2 * j] = make_float2(v, v);
    }
    // per-thread bias registers (8 cols)
    float biasv[8];
    #pragma unroll
    for (int cc = 0; cc < 8; cc++) biasv[cc] = b_ih[cg * 8 + cc] + b_hh[cg * 8 + cc];

    const float* pWl = sW + cg * 16;
    const float* pXl = sX + rg * 4;

    const int m_base = blockIdx.x * 256;
    for (int blk = 0; blk < 4; blk++) {
        const int m0 = m_base + blk * 64;
        __syncthreads();   // first iter: also covers the sW build above
        // stage x transposed: sX[i][r] = x[(m0+r)*64 + i]
        #pragma unroll
        for (int it = 0; it < 16; it++) {
            int idx = tid + it * 256;
            int r = idx >> 6, i = idx & 63;
            sX[i * 68 + r] = x[(size_t)(m0 + r) * IDIM + i];
        }
        __syncthreads();

        u64t acc[2][8];
        #pragma unroll
        for (int a = 0; a < 2; a++)
            #pragma unroll
            for (int c = 0; c < 8; c++) acc[a][c] = 0ULL;

        #pragma unroll 8
        for (int k = 0; k < 64; k++) {
            ulonglong2 xv = *(const ulonglong2*)(pXl + k * 68);  // rows (4rg,4rg+1),(4rg+2,4rg+3)
            #pragma unroll
            for (int cp = 0; cp < 4; cp++) {
                ulonglong2 wv = *(const ulonglong2*)(pWl + k * 256 + cp * 4);  // splat(W[c]),splat(W[c+1])
                acc[0][2 * cp]     = ffma2(xv.x, wv.x, acc[0][2 * cp]);
                acc[1][2 * cp]     = ffma2(xv.y, wv.x, acc[1][2 * cp]);
                acc[0][2 * cp + 1] = ffma2(xv.x, wv.y, acc[0][2 * cp + 1]);
                acc[1][2 * cp + 1] = ffma2(xv.y, wv.y, acc[1][2 * cp + 1]);
            }
        }

        // epilogue: write xp[t][b][cols]
        #pragma unroll
        for (int rr = 0; rr < 4; rr++) {
            int m = m0 + rg * 4 + rr;
            int bb = m >> 10;          // batch
            int tt = m & 1023;         // timestep
            float* dst = g_xp + ((size_t)tt * BATCH + bb) * HDIM + cg * 8;
            int rp = rr >> 1, hi = rr & 1;
            float4 o0, o1;
            o0.x = (hi ? f2hi(acc[rp][0]) : f2lo(acc[rp][0])) + biasv[0];
            o0.y = (hi ? f2hi(acc[rp][1]) : f2lo(acc[rp][1])) + biasv[1];
            o0.z = (hi ? f2hi(acc[rp][2]) : f2lo(acc[rp][2])) + biasv[2];
            o0.w = (hi ? f2hi(acc[rp][3]) : f2lo(acc[rp][3])) + biasv[3];
            o1.x = (hi ? f2hi(acc[rp][4]) : f2lo(acc[rp][4])) + biasv[4];
            o1.y = (hi ? f2hi(acc[rp][5]) : f2lo(acc[rp][5])) + biasv[5];
            o1.z = (hi ? f2hi(acc[rp][6]) : f2lo(acc[rp][6])) + biasv[6];
            o1.w = (hi ? f2hi(acc[rp][7]) : f2lo(acc[rp][7])) + biasv[7];
            *(float4*)dst = o0;
            *(float4*)(dst + 4) = o1;
        }
    }
}

// ---------------------------------------------------------------------------
// Kernel 2: persistent recurrence. 128 CTAs x 256 threads, 4 batch rows/CTA.
// thread: j = tid & 127 (output unit), bp = tid >> 7 (handles batches 2bp, 2bp+1)
// W_hh row j (all 128 k) lives in 64 packed f32x2 registers.
// h double-buffered in shared; all h loads are full-warp broadcasts (N=1).
// No shuffle reduce — each thread owns the full K reduction.
// ---------------------------------------------------------------------------
__global__ void __launch_bounds__(256, 1) rnn_kernel(
    const float* __restrict__ W_hh,
    const float* __restrict__ fc_w,
    const float* __restrict__ fc_b,
    float* __restrict__ out)
{
    __shared__ __align__(16) float hbuf[2][4][HDIM];   // [buf][b][k]

    const int tid = threadIdx.x;
    const int warp = tid >> 5, lane = tid & 31;
    const int j = tid & 127;
    const int bp = tid >> 7;          // 0 or 1
    const int b0 = 2 * bp, b1 = 2 * bp + 1;
    const int row0 = blockIdx.x * 4;

    // W_hh[j][0..127] -> 64 packed f32x2 registers
    u64t w[64];
    {
        const ulonglong2* src = (const ulonglong2*)(W_hh + j * HDIM);
        #pragma unroll
        for (int q = 0; q < 32; q++) {
            ulonglong2 v = src[q];
            w[2 * q] = v.x;
            w[2 * q + 1] = v.y;
        }
    }

    // h0 = 0
    for (int i = tid; i < 2 * 4 * HDIM; i += 256) ((float*)hbuf)[i] = 0.f;

    float cur0, cur1, nxt0, nxt1;
    {
        const float* p0 = g_xp + ((size_t)0 * BATCH + row0) * HDIM + j;   // t = 0
        cur0 = __ldg(p0 + b0 * HDIM);
        cur1 = __ldg(p0 + b1 * HDIM);
    }
    __syncthreads();

    int p = 0;
    #pragma unroll 1
    for (int t = 0; t < TSTEPS; t++) {
        // prefetch next step's xp (latency hidden behind this step's compute)
        {
            int t1 = (t + 1 < TSTEPS) ? t + 1 : t;
            const float* pn = g_xp + ((size_t)t1 * BATCH + row0) * HDIM + j;
            nxt0 = __ldg(pn + b0 * HDIM);
            nxt1 = __ldg(pn + b1 * HDIM);
        }

        u64t acc0 = 0ULL, acc1 = 0ULL;
        const float* h0v = &hbuf[p][b0][0];
        const float* h1v = &hbuf[p][b1][0];
        #pragma unroll
        for (int c = 0; c < 32; c++) {
            ulonglong2 v0 = *(const ulonglong2*)(h0v + c * 4);   // broadcast
            ulonglong2 v1 = *(const ulonglong2*)(h1v + c * 4);   // broadcast
            acc0 = ffma2(v0.x, w[2 * c], acc0);
            acc1 = ffma2(v1.x, w[2 * c], acc1);
            acc0 = ffma2(v0.y, w[2 * c + 1], acc0);
            acc1 = ffma2(v1.y, w[2 * c + 1], acc1);
        }

        float s0 = f2lo(acc0) + f2hi(acc0);
        float s1 = f2lo(acc1) + f2hi(acc1);
        float h0 = tanh_ap(s0 + cur0);
        float h1 = tanh_ap(s1 + cur1);
        hbuf[p ^ 1][b0][j] = h0;
        hbuf[p ^ 1][b1][j] = h1;
        cur0 = nxt0;
        cur1 = nxt1;
        __syncthreads();
        p ^= 1;
    }

    // fc + sigmoid epilogue: warp b handles batch row b
    if (warp < 4) {
        const int b = warp;
        float s = 0.f;
        #pragma unroll
        for (int i = lane; i < HDIM; i += 32)
            s += hbuf[p][b][i] * fc_w[i];
        #pragma unroll
        for (int o = 16; o > 0; o >>= 1) s += __shfl_xor_sync(0xffffffffu, s, o);
        if (lane == 0) out[row0 + b] = 1.f / (1.f + __expf(-(s + fc_b[0])));
    }
}

// ---------------------------------------------------------------------------
extern "C" void kernel_launch(void* const* d_in, const int* in_sizes, int n_in,
                              void* d_out, int out_size)
{
    const float* x    = (const float*)d_in[0];
    const float* W_ih = (const float*)d_in[1];
    const float* W_hh = (const float*)d_in[2];
    const float* b_ih = (const float*)d_in[3];
    const float* b_hh = (const float*)d_in[4];
    const float* fc_w = (const float*)d_in[5];
    const float* fc_b = (const float*)d_in[6];
    float* out = (float*)d_out;

    const int smem_bytes = (64 * 256 + 64 * 68) * 4;   // 82944
    cudaFuncSetAttribute(xproj_kernel, cudaFuncAttributeMaxDynamicSharedMemorySize, smem_bytes);

    xproj_kernel<<<2048, 256, smem_bytes>>>(x, W_ih, b_ih, b_hh);
    rnn_kernel<<<128, 256>>>(W_hh, fc_w, fc_b, out);
}

// round 3
// speedup vs baseline: 1.4073x; 1.4073x over previous
#include <cuda_runtime.h>
#include <cstdint>

#define BATCH 512
#define TSTEPS 1024
#define IDIM 64
#define HDIM 128

// Scratch (static __device__ arrays — no allocation in kernel_launch)
__device__ float g_xp[(size_t)TSTEPS * BATCH * HDIM];   // [t][b][h]  268 MB

typedef unsigned long long u64t;

__device__ __forceinline__ u64t ffma2(u64t a, u64t b, u64t c) {
    u64t d;
    asm("fma.rn.f32x2 %0, %1, %2, %3;" : "=l"(d) : "l"(a), "l"(b), "l"(c));
    return d;
}
__device__ __forceinline__ float f2lo(u64t v) { return __uint_as_float((unsigned)(v & 0xffffffffULL)); }
__device__ __forceinline__ float f2hi(u64t v) { return __uint_as_float((unsigned)(v >> 32)); }
__device__ __forceinline__ float tanh_ap(float x) {
    float y;
    asm("tanh.approx.f32 %0, %1;" : "=f"(y) : "f"(x));
    return y;
}

// ---------------------------------------------------------------------------
// Kernel 1: xp[t][b][j] = sum_i x[b][t][i] * W_ih[j][i] + (b_ih[j]+b_hh[j])
// 256 threads, CTA tile = 256 rows (4 blocks of 64) x 128 cols.
// thread (cg=tid>>4, rg=tid&15): 4 rows x 8 cols, f32x2 packed over row pairs.
// ---------------------------------------------------------------------------
__global__ void __launch_bounds__(256, 2) xproj_kernel(
    const float* __restrict__ x,
    const float* __restrict__ W_ih,
    const float* __restrict__ b_ih,
    const float* __restrict__ b_hh)
{
    extern __shared__ float smem[];
    float* sW = smem;               // [64][256]  (splatted W: sW[k][2j]=sW[k][2j+1]=W_ih[j][k])
    float* sX = smem + 64 * 256;    // [64][68]   (x transposed, padded)

    const int tid = threadIdx.x;
    const int cg = tid >> 4;        // 0..15 -> cols cg*8..cg*8+7
    const int rg = tid & 15;        // 0..15 -> rows rg*4..rg*4+3

    // Build splatted W in shared directly from W_ih (coalesced reads).
    #pragma unroll
    for (int i = 0; i < 32; i++) {
        int idx = tid + i * 256;     // 0..8191
        int j = idx >> 6;            // 0..127
        int k = idx & 63;            // 0..63
        float v = W_ih[idx];
        *(float2*)&sW[k * 256 + 2 * j] = make_float2(v, v);
    }
    // per-thread bias registers (8 cols)
    float biasv[8];
    #pragma unroll
    for (int cc = 0; cc < 8; cc++) biasv[cc] = b_ih[cg * 8 + cc] + b_hh[cg * 8 + cc];

    const float* pWl = sW + cg * 16;
    const float* pXl = sX + rg * 4;

    const int m_base = blockIdx.x * 256;
    for (int blk = 0; blk < 4; blk++) {
        const int m0 = m_base + blk * 64;
        __syncthreads();   // first iter: also covers the sW build above
        // stage x transposed: sX[i][r] = x[(m0+r)*64 + i]
        #pragma unroll
        for (int it = 0; it < 16; it++) {
            int idx = tid + it * 256;
            int r = idx >> 6, i = idx & 63;
            sX[i * 68 + r] = x[(size_t)(m0 + r) * IDIM + i];
        }
        __syncthreads();

        u64t acc[2][8];
        #pragma unroll
        for (int a = 0; a < 2; a++)
            #pragma unroll
            for (int c = 0; c < 8; c++) acc[a][c] = 0ULL;

        #pragma unroll 8
        for (int k = 0; k < 64; k++) {
            ulonglong2 xv = *(const ulonglong2*)(pXl + k * 68);  // rows (4rg,4rg+1),(4rg+2,4rg+3)
            #pragma unroll
            for (int cp = 0; cp < 4; cp++) {
                ulonglong2 wv = *(const ulonglong2*)(pWl + k * 256 + cp * 4);  // splat(W[c]),splat(W[c+1])
                acc[0][2 * cp]     = ffma2(xv.x, wv.x, acc[0][2 * cp]);
                acc[1][2 * cp]     = ffma2(xv.y, wv.x, acc[1][2 * cp]);
                acc[0][2 * cp + 1] = ffma2(xv.x, wv.y, acc[0][2 * cp + 1]);
                acc[1][2 * cp + 1] = ffma2(xv.y, wv.y, acc[1][2 * cp + 1]);
            }
        }

        // epilogue: write xp[t][b][cols]
        #pragma unroll
        for (int rr = 0; rr < 4; rr++) {
            int m = m0 + rg * 4 + rr;
            int bb = m >> 10;          // batch
            int tt = m & 1023;         // timestep
            float* dst = g_xp + ((size_t)tt * BATCH + bb) * HDIM + cg * 8;
            int rp = rr >> 1, hi = rr & 1;
            float4 o0, o1;
            o0.x = (hi ? f2hi(acc[rp][0]) : f2lo(acc[rp][0])) + biasv[0];
            o0.y = (hi ? f2hi(acc[rp][1]) : f2lo(acc[rp][1])) + biasv[1];
            o0.z = (hi ? f2hi(acc[rp][2]) : f2lo(acc[rp][2])) + biasv[2];
            o0.w = (hi ? f2hi(acc[rp][3]) : f2lo(acc[rp][3])) + biasv[3];
            o1.x = (hi ? f2hi(acc[rp][4]) : f2lo(acc[rp][4])) + biasv[4];
            o1.y = (hi ? f2hi(acc[rp][5]) : f2lo(acc[rp][5])) + biasv[5];
            o1.z = (hi ? f2hi(acc[rp][6]) : f2lo(acc[rp][6])) + biasv[6];
            o1.w = (hi ? f2hi(acc[rp][7]) : f2lo(acc[rp][7])) + biasv[7];
            *(float4*)dst = o0;
            *(float4*)(dst + 4) = o1;
        }
    }
}

// ---------------------------------------------------------------------------
// Kernel 2: persistent recurrence. 256 CTAs x 256 threads, 2 batch rows/CTA,
// 2 CTAs/SM so barrier/memory stalls of one CTA overlap the other's compute.
// Warp layout: jl=lane&15, kh=lane>>4 (k-half), j=warp*16+jl.
// W_hh row j (one k-half, 64 floats) lives in 32 packed f32x2 registers.
// xp prefetched DEPTH=4 steps ahead in a rotating register pipeline.
// h double-buffered in shared with a 4-float pad between k-halves
// (keeps the two broadcast groups of an LDS.128 on distinct banks).
// ---------------------------------------------------------------------------
__global__ void __launch_bounds__(256, 2) rnn_kernel(
    const float* __restrict__ W_hh,
    const float* __restrict__ fc_w,
    const float* __restrict__ fc_b,
    float* __restrict__ out)
{
    __shared__ __align__(16) float hbuf[2][2][136];   // [buf][b][k + 4*(k>=64)]

    const int tid = threadIdx.x;
    const int warp = tid >> 5, lane = tid & 31;
    const int kh = lane >> 4, jl = lane & 15;
    const int j = warp * 16 + jl;
    const int jphys = j + (j >= 64 ? 4 : 0);
    const int row0 = blockIdx.x * 2;

    // W_hh[j][kh*64 .. kh*64+63] -> 32 packed f32x2 registers
    u64t w[32];
    {
        const ulonglong2* src = (const ulonglong2*)(W_hh + j * HDIM + kh * 64);
        #pragma unroll
        for (int q = 0; q < 16; q++) {
            ulonglong2 v = src[q];
            w[2 * q] = v.x;
            w[2 * q + 1] = v.y;
        }
    }

    // h0 = 0
    for (int i = tid; i < 2 * 2 * 136; i += 256) ((float*)hbuf)[i] = 0.f;

    // xp prefetch pipeline, depth 4 (kh==0 lanes only)
    float pre0[4], pre1[4];
    if (kh == 0) {
        #pragma unroll
        for (int d = 0; d < 4; d++) {
            const float* pp = g_xp + ((size_t)d * BATCH + row0) * HDIM + j;
            pre0[d] = __ldg(pp);
            pre1[d] = __ldg(pp + HDIM);
        }
    }
    __syncthreads();

    int p = 0;
    #pragma unroll 1
    for (int tt = 0; tt < TSTEPS; tt += 4) {
        #pragma unroll
        for (int u = 0; u < 4; u++) {
            const int t = tt + u;
            float cur0 = pre0[u], cur1 = pre1[u];
            if (kh == 0) {
                int t4 = (t + 4 < TSTEPS) ? t + 4 : t;   // clamp: stale loads unused
                const float* pn = g_xp + ((size_t)t4 * BATCH + row0) * HDIM + j;
                pre0[u] = __ldg(pn);
                pre1[u] = __ldg(pn + HDIM);
            }

            u64t acc0 = 0ULL, acc1 = 0ULL;
            const float* hb = &hbuf[p][0][kh * 68];
            #pragma unroll
            for (int c = 0; c < 16; c++) {
                ulonglong2 v0 = *(const ulonglong2*)(hb + c * 4);        // b0, broadcast grp
                ulonglong2 v1 = *(const ulonglong2*)(hb + 136 + c * 4);  // b1, broadcast grp
                acc0 = ffma2(v0.x, w[2 * c], acc0);
                acc1 = ffma2(v1.x, w[2 * c], acc1);
                acc0 = ffma2(v0.y, w[2 * c + 1], acc0);
                acc1 = ffma2(v1.y, w[2 * c + 1], acc1);
            }

            float s0 = f2lo(acc0) + f2hi(acc0);
            float s1 = f2lo(acc1) + f2hi(acc1);
            s0 += __shfl_xor_sync(0xffffffffu, s0, 16);   // combine k-halves
            s1 += __shfl_xor_sync(0xffffffffu, s1, 16);
            if (kh == 0) {
                hbuf[p ^ 1][0][jphys] = tanh_ap(s0 + cur0);
                hbuf[p ^ 1][1][jphys] = tanh_ap(s1 + cur1);
            }
            __syncthreads();
            p ^= 1;
        }
    }

    // fc + sigmoid epilogue: warp b handles batch row b
    if (warp < 2) {
        const int b = warp;
        float s = 0.f;
        #pragma unroll
        for (int i = lane; i < HDIM; i += 32)
            s += hbuf[p][b][i + (i >= 64 ? 4 : 0)] * fc_w[i];
        #pragma unroll
        for (int o = 16; o > 0; o >>= 1) s += __shfl_xor_sync(0xffffffffu, s, o);
        if (lane == 0) out[row0 + b] = 1.f / (1.f + __expf(-(s + fc_b[0])));
    }
}

// ---------------------------------------------------------------------------
extern "C" void kernel_launch(void* const* d_in, const int* in_sizes, int n_in,
                              void* d_out, int out_size)
{
    const float* x    = (const float*)d_in[0];
    const float* W_ih = (const float*)d_in[1];
    const float* W_hh = (const float*)d_in[2];
    const float* b_ih = (const float*)d_in[3];
    const float* b_hh = (const float*)d_in[4];
    const float* fc_w = (const float*)d_in[5];
    const float* fc_b = (const float*)d_in[6];
    float* out = (float*)d_out;

    const int smem_bytes = (64 * 256 + 64 * 68) * 4;   // 82944
    cudaFuncSetAttribute(xproj_kernel, cudaFuncAttributeMaxDynamicSharedMemorySize, smem_bytes);

    xproj_kernel<<<2048, 256, smem_bytes>>>(x, W_ih, b_ih, b_hh);
    rnn_kernel<<<256, 256>>>(W_hh, fc_w, fc_b, out);
}

// round 4
// speedup vs baseline: 1.8247x; 1.2966x over previous
#include <cuda_runtime.h>
#include <cstdint>

#define BATCH 512
#define TSTEPS 1024
#define IDIM 64
#define HDIM 128

typedef unsigned long long u64t;

__device__ __forceinline__ u64t ffma2(u64t a, u64t b, u64t c) {
    u64t d;
    asm("fma.rn.f32x2 %0, %1, %2, %3;" : "=l"(d) : "l"(a), "l"(b), "l"(c));
    return d;
}
__device__ __forceinline__ u64t pk(float a, float b) {
    u64t r; asm("mov.b64 %0, {%1, %2};" : "=l"(r) : "f"(a), "f"(b)); return r;
}
__device__ __forceinline__ float hadd2(u64t v) {
    float x, y;
    asm("mov.b64 {%0, %1}, %2;" : "=f"(x), "=f"(y) : "l"(v));
    return x + y;
}
__device__ __forceinline__ float tanh_ap(float x) {
    float y; asm("tanh.approx.f32 %0, %1;" : "=f"(y) : "f"(x)); return y;
}

// ---------------------------------------------------------------------------
// Fully fused RNN: 256 CTAs x 256 threads, 2 batch rows per CTA, 2 CTAs/SM.
// Per step t:   h_t[b][j] = tanh( sum_k W_hh[j][k] h_{t-1}[b][k]
//                               + sum_i W_ih[j][i] x[b][t][i] + bias[j] )
// Thread tiling: lane -> (kq = lane>>3: k-quarter of 32 / i-range of 16,
//                         jl = lane&7), warp w -> j0 = w*16+jl, j1 = j0+8.
// Each thread: 2 j x 2 b partials over its kq slice; shfl_xor(8,16) reduce.
// W_hh (64 regs) + W_ih (32 regs) live in registers.
// h double-buffered in shared, stride 144 (4-float pad per 32 k) so the four
// kq broadcast groups of each LDS.128 hit disjoint banks.
// x staged in 16-step tiles via cp.async double buffer; x-chunk reads rotated
// by kq ((cc+kq)&3, weights pre-rotated) for conflict-free LDS.
// ---------------------------------------------------------------------------

#define HSTR 144                       // padded h row stride (floats)
#define SX_B_STRIDE (16 * IDIM)        // 1024 floats per batch per tile buf
#define SX_BUF_BYTES (2 * 16 * IDIM * 4)  // 8192

struct StepCtx {
    u64t whh[2][16];   // [jj][2c+p]  k = 32kq + 4c + {0..3}
    u64t wih[2][8];    // [jj][2cc+p] rotated chunks
    int  xoff[4];      // float offsets within 16-float i-slice (rotated)
    int  lane, j0p, j1p;
    float bias0, bias1;
};

__device__ __forceinline__ void do_step(
    const StepCtx& C,
    const float* __restrict__ hr,   // read h buffer base (+36*kq pre-added by caller? no: raw)
    float* __restrict__ hw,
    const float* __restrict__ xb0,  // &sx[s][0][t][16*kq]
    const float* __restrict__ xb1,  // &sx[s][1][t][16*kq]
    int kq36)
{
    u64t a00 = 0, a01 = 0, a10 = 0, a11 = 0;   // a[jj][bb]
    const float* hb0 = hr + kq36;
    const float* hb1 = hr + HSTR + kq36;
    #pragma unroll
    for (int c = 0; c < 8; c++) {
        ulonglong2 h0 = *(const ulonglong2*)(hb0 + 4 * c);
        ulonglong2 h1 = *(const ulonglong2*)(hb1 + 4 * c);
        a00 = ffma2(h0.x, C.whh[0][2 * c],     a00);
        a10 = ffma2(h0.x, C.whh[1][2 * c],     a10);
        a00 = ffma2(h0.y, C.whh[0][2 * c + 1], a00);
        a10 = ffma2(h0.y, C.whh[1][2 * c + 1], a10);
        a01 = ffma2(h1.x, C.whh[0][2 * c],     a01);
        a11 = ffma2(h1.x, C.whh[1][2 * c],     a11);
        a01 = ffma2(h1.y, C.whh[0][2 * c + 1], a01);
        a11 = ffma2(h1.y, C.whh[1][2 * c + 1], a11);
    }
    #pragma unroll
    for (int cc = 0; cc < 4; cc++) {
        ulonglong2 x0 = *(const ulonglong2*)(xb0 + C.xoff[cc]);
        ulonglong2 x1 = *(const ulonglong2*)(xb1 + C.xoff[cc]);
        a00 = ffma2(x0.x, C.wih[0][2 * cc],     a00);
        a10 = ffma2(x0.x, C.wih[1][2 * cc],     a10);
        a00 = ffma2(x0.y, C.wih[0][2 * cc + 1], a00);
        a10 = ffma2(x0.y, C.wih[1][2 * cc + 1], a10);
        a01 = ffma2(x1.x, C.wih[0][2 * cc],     a01);
        a11 = ffma2(x1.x, C.wih[1][2 * cc],     a11);
        a01 = ffma2(x1.y, C.wih[0][2 * cc + 1], a01);
        a11 = ffma2(x1.y, C.wih[1][2 * cc + 1], a11);
    }

    float s00 = hadd2(a00), s01 = hadd2(a01);
    float s10 = hadd2(a10), s11 = hadd2(a11);
    s00 += __shfl_xor_sync(0xffffffffu, s00, 8);
    s01 += __shfl_xor_sync(0xffffffffu, s01, 8);
    s10 += __shfl_xor_sync(0xffffffffu, s10, 8);
    s11 += __shfl_xor_sync(0xffffffffu, s11, 8);
    s00 += __shfl_xor_sync(0xffffffffu, s00, 16);
    s01 += __shfl_xor_sync(0xffffffffu, s01, 16);
    s10 += __shfl_xor_sync(0xffffffffu, s10, 16);
    s11 += __shfl_xor_sync(0xffffffffu, s11, 16);

    if (C.lane < 8) {
        hw[C.j0p]        = tanh_ap(s00 + C.bias0);
        hw[HSTR + C.j0p] = tanh_ap(s01 + C.bias0);
        hw[C.j1p]        = tanh_ap(s10 + C.bias1);
        hw[HSTR + C.j1p] = tanh_ap(s11 + C.bias1);
    }
    __syncthreads();
}

__global__ void __launch_bounds__(256, 2) rnn_fused(
    const float* __restrict__ x,
    const float* __restrict__ W_ih,
    const float* __restrict__ W_hh,
    const float* __restrict__ b_ih,
    const float* __restrict__ b_hh,
    const float* __restrict__ fc_w,
    const float* __restrict__ fc_b,
    float* __restrict__ out)
{
    __shared__ __align__(16) float sx[2][2][16][IDIM];   // 16 KB (double buffer)
    __shared__ __align__(16) float hbuf[2][2][HSTR];     // ping-pong h

    const int tid  = threadIdx.x;
    const int warp = tid >> 5, lane = tid & 31;
    const int kq   = lane >> 3;
    const int jl   = lane & 7;
    const int j0   = warp * 16 + jl;
    const int j1   = j0 + 8;
    const int row0 = blockIdx.x * 2;

    StepCtx C;
    C.lane = lane;
    C.j0p = j0 + ((j0 >> 5) << 2);
    C.j1p = j1 + ((j1 >> 5) << 2);
    C.bias0 = b_ih[j0] + b_hh[j0];
    C.bias1 = b_ih[j1] + b_hh[j1];
    const int kq36 = 36 * kq;

    // ---- load weights into registers ----
    #pragma unroll
    for (int jj = 0; jj < 2; jj++) {
        const float4* wr = (const float4*)(W_hh + (size_t)(jj ? j1 : j0) * HDIM + 32 * kq);
        #pragma unroll
        for (int c = 0; c < 8; c++) {
            float4 v = __ldg(wr + c);
            C.whh[jj][2 * c]     = pk(v.x, v.y);
            C.whh[jj][2 * c + 1] = pk(v.z, v.w);
        }
    }
    #pragma unroll
    for (int jj = 0; jj < 2; jj++) {
        const float4* wr = (const float4*)(W_ih + (size_t)(jj ? j1 : j0) * IDIM + 16 * kq);
        #pragma unroll
        for (int cc = 0; cc < 4; cc++) {
            int cl = (cc + kq) & 3;
            float4 v = __ldg(wr + cl);
            C.wih[jj][2 * cc]     = pk(v.x, v.y);
            C.wih[jj][2 * cc + 1] = pk(v.z, v.w);
        }
    }
    #pragma unroll
    for (int cc = 0; cc < 4; cc++) C.xoff[cc] = 4 * ((cc + kq) & 3);

    // ---- zero h buffers ----
    for (int i = tid; i < 2 * 2 * HSTR; i += 256) (&hbuf[0][0][0])[i] = 0.f;

    // ---- x staging slots (2 x 16B cp.async per thread per tile) ----
    const float* gsrc[2];
    unsigned     sdst[2];
    #pragma unroll
    for (int r = 0; r < 2; r++) {
        int idx = tid + 256 * r;          // 0..511
        int bb = idx >> 8;                // batch within CTA
        int rem = idx & 255;
        int tt = rem >> 4, f4 = rem & 15;
        gsrc[r] = x + ((size_t)(row0 + bb) * TSTEPS + tt) * IDIM + f4 * 4;
        sdst[r] = (unsigned)__cvta_generic_to_shared(&sx[0][bb][tt][f4 * 4]);
    }

    // stage tile 0 into buffer 0
    #pragma unroll
    for (int r = 0; r < 2; r++)
        asm volatile("cp.async.cg.shared.global [%0], [%1], 16;"
                     :: "r"(sdst[r]), "l"(gsrc[r]) : "memory");
    asm volatile("cp.async.commit_group;" ::: "memory");
    asm volatile("cp.async.wait_group 0;" ::: "memory");
    __syncthreads();

    float* hA = &hbuf[0][0][0];
    float* hB = &hbuf[1][0][0];

    int s = 0;
    #pragma unroll 1
    for (int tile = 0; tile < TSTEPS / 16; tile++) {
        // prefetch next tile into the other buffer
        if (tile + 1 < TSTEPS / 16) {
            size_t goff = (size_t)(tile + 1) * 16 * IDIM;
            unsigned soff = (s ^ 1) * SX_BUF_BYTES;
            #pragma unroll
            for (int r = 0; r < 2; r++)
                asm volatile("cp.async.cg.shared.global [%0], [%1], 16;"
                             :: "r"(sdst[r] + soff), "l"(gsrc[r] + goff) : "memory");
        }
        asm volatile("cp.async.commit_group;" ::: "memory");

        const float* xb = &sx[s][0][0][16 * kq];
        #pragma unroll 1
        for (int m = 0; m < 4; m++) {
            const float* x0 = xb + (m * 4) * IDIM;
            const float* x1 = x0 + SX_B_STRIDE;
            do_step(C, hA, hB, x0,            x1,            kq36);
            do_step(C, hB, hA, x0 + IDIM,     x1 + IDIM,     kq36);
            do_step(C, hA, hB, x0 + 2 * IDIM, x1 + 2 * IDIM, kq36);
            do_step(C, hB, hA, x0 + 3 * IDIM, x1 + 3 * IDIM, kq36);
        }
        asm volatile("cp.async.wait_group 0;" ::: "memory");
        __syncthreads();
        s ^= 1;
    }

    // final h (t = 1023, odd) lives in hbuf[0]
    if (warp < 2) {
        const int b = warp;
        float sum = 0.f;
        #pragma unroll
        for (int i = lane; i < HDIM; i += 32)
            sum += hbuf[0][b][i + ((i >> 5) << 2)] * fc_w[i];
        #pragma unroll
        for (int o = 16; o > 0; o >>= 1) sum += __shfl_xor_sync(0xffffffffu, sum, o);
        if (lane == 0) out[row0 + b] = 1.f / (1.f + __expf(-(sum + fc_b[0])));
    }
}

// ---------------------------------------------------------------------------
extern "C" void kernel_launch(void* const* d_in, const int* in_sizes, int n_in,
                              void* d_out, int out_size)
{
    const float* x    = (const float*)d_in[0];
    const float* W_ih = (const float*)d_in[1];
    const float* W_hh = (const float*)d_in[2];
    const float* b_ih = (const float*)d_in[3];
    const float* b_hh = (const float*)d_in[4];
    const float* fc_w = (const float*)d_in[5];
    const float* fc_b = (const float*)d_in[6];
    float* out = (float*)d_out;

    rnn_fused<<<BATCH / 2, 256>>>(x, W_ih, W_hh, b_ih, b_hh, fc_w, fc_b, out);
}